// round 2
// baseline (speedup 1.0000x reference)
#include <cuda_runtime.h>
#include <cstdint>
#include <cstring>

// ---------------------------------------------------------------------------
// MultiQueryAttention: out = (softmax((x@Wq) Kᵀ / sqrt(d)) V) @ Wo + bo
// B=4, T=2048, H=16, d=128, model=2048.  All fp32, packed f32x2 FMA pipes.
// Stage 1: Q = query@Wq + bq            (SGEMM 8192x2048x2048)
// Stage 2: flash attention per (b,h)    (online softmax, 64x64 tiles)
// Stage 3: out = attn@Wo + bo           (SGEMM 8192x2048x2048)
// ---------------------------------------------------------------------------

#define BATCH 4
#define SEQ   2048
#define NHEAD 16
#define HDIM  128
#define MODEL 2048  // NHEAD*HDIM

// scratch (allocation-free rule: __device__ globals)
__device__ float g_q[(size_t)BATCH * SEQ * MODEL];     // [b,t,h,d] = [8192,2048]
__device__ float g_attn[(size_t)BATCH * SEQ * MODEL];  // [b,t,h,d]

// ---------------- packed f32x2 helpers (Blackwell dual-fp32 pipe) ----------
__device__ __forceinline__ unsigned long long pack2(float lo, float hi) {
    unsigned long long r;
    asm("mov.b64 %0, {%1, %2};" : "=l"(r) : "f"(lo), "f"(hi));
    return r;
}
__device__ __forceinline__ float2 unpack2(unsigned long long v) {
    float2 r;
    asm("mov.b64 {%0, %1}, %2;" : "=f"(r.x), "=f"(r.y) : "l"(v));
    return r;
}
__device__ __forceinline__ void ffma2(unsigned long long& d,
                                      unsigned long long a,
                                      unsigned long long b) {
    asm("fma.rn.f32x2 %0, %1, %2, %0;" : "+l"(d) : "l"(a), "l"(b));
}
__device__ __forceinline__ unsigned long long fmul2(unsigned long long a,
                                                    unsigned long long b) {
    unsigned long long r;
    asm("mul.rn.f32x2 %0, %1, %2;" : "=l"(r) : "l"(a), "l"(b));
    return r;
}

// ---------------------------------------------------------------------------
// SGEMM with bias: C[M,N] = A[M,K] @ B[K,N] + bias[N]
// 128x128 block tile, BK=8, 256 threads, 8x8 per thread, acc packed over j.
// Assumes M%128==0, N%128==0, K%8==0 (true here).
// ---------------------------------------------------------------------------
__global__ __launch_bounds__(256) void sgemm_bias_kernel(
    const float* __restrict__ A, const float* __restrict__ Bm,
    const float* __restrict__ bias, float* __restrict__ C,
    int M, int N, int K)
{
    __shared__ __align__(16) float As[8][128];  // transposed: As[k][row]
    __shared__ __align__(16) float Bs[8][128];  // Bs[k][col]

    const int tid = threadIdx.x;
    const int tx = tid & 15;
    const int ty = tid >> 4;
    const int row0 = blockIdx.y * 128;
    const int col0 = blockIdx.x * 128;

    // load mapping
    const int arow = tid >> 1;            // 0..127
    const int acol = (tid & 1) << 2;      // 0 or 4
    const int brow = tid >> 5;            // 0..7
    const int bcol = (tid & 31) << 2;     // 0..124

    const float* Ap = A + (size_t)(row0 + arow) * K + acol;
    const float* Bp = Bm + (size_t)brow * N + col0 + bcol;

    unsigned long long acc[8][4];
#pragma unroll
    for (int i = 0; i < 8; i++)
#pragma unroll
        for (int j = 0; j < 4; j++) acc[i][j] = 0ull;

    float4 av = *(const float4*)Ap;
    float4 bv = *(const float4*)Bp;

    for (int k0 = 0; k0 < K; k0 += 8) {
        As[acol + 0][arow] = av.x;
        As[acol + 1][arow] = av.y;
        As[acol + 2][arow] = av.z;
        As[acol + 3][arow] = av.w;
        *(float4*)&Bs[brow][bcol] = bv;
        __syncthreads();

        if (k0 + 8 < K) {  // register prefetch of next tile
            av = *(const float4*)(Ap + k0 + 8);
            bv = *(const float4*)(Bp + (size_t)(k0 + 8) * N);
        }

#pragma unroll
        for (int kk = 0; kk < 8; kk++) {
            float a[8];
            *(float4*)(a)     = *(const float4*)&As[kk][ty * 8];
            *(float4*)(a + 4) = *(const float4*)&As[kk][ty * 8 + 4];
            ulonglong2 b01 = *(const ulonglong2*)&Bs[kk][tx * 8];
            ulonglong2 b23 = *(const ulonglong2*)&Bs[kk][tx * 8 + 4];
            unsigned long long bb[4] = {b01.x, b01.y, b23.x, b23.y};
#pragma unroll
            for (int i = 0; i < 8; i++) {
                unsigned long long aa = pack2(a[i], a[i]);
#pragma unroll
                for (int j = 0; j < 4; j++) ffma2(acc[i][j], aa, bb[j]);
            }
        }
        __syncthreads();
    }

#pragma unroll
    for (int i = 0; i < 8; i++) {
        int row = row0 + ty * 8 + i;
#pragma unroll
        for (int j = 0; j < 4; j++) {
            int col = col0 + tx * 8 + j * 2;
            float2 v = unpack2(acc[i][j]);
            v.x += bias[col];
            v.y += bias[col + 1];
            *(float2*)&C[(size_t)row * N + col] = v;
        }
    }
}

// ---------------------------------------------------------------------------
// Flash attention per (b, h): 64 query rows per block, 64-key tiles,
// online softmax. K and V alias one smem buffer (loaded back-to-back).
//   Qs  [64][132]  (row-major, padded for conflict-free k-vector reads)
//   KVs [64][132]  (K tile, then V tile)
//   Ps  [64][80]   (exp'd logits tile; stride 80 => conflict-free STS)
// Thread map: tx=tid&15, ty=tid>>4; rows {ty+16i}, cols {tx+16j} (strided).
// S-GEMM packs the K-reduction in f32x2 pairs (both operands contiguous).
// ---------------------------------------------------------------------------
#define QS_STRIDE 132
#define PS_STRIDE 80
#define ATTN_SMEM ((2 * 64 * QS_STRIDE + 64 * PS_STRIDE) * (int)sizeof(float))

__global__ __launch_bounds__(256) void mqa_attn_kernel(
    const float* __restrict__ qp, const float* __restrict__ kp,
    const float* __restrict__ vp, float* __restrict__ op)
{
    extern __shared__ float sm[];
    float* Qs  = sm;                        // [64][132]
    float* KVs = sm + 64 * QS_STRIDE;       // [64][132]
    float* Ps  = sm + 2 * 64 * QS_STRIDE;   // [64][80]

    const int tid = threadIdx.x;
    const int tx = tid & 15;
    const int ty = tid >> 4;
    const int q0 = blockIdx.x * 64;
    const int h  = blockIdx.y;
    const int b  = blockIdx.z;

    const float* qbase = qp + (((size_t)b * SEQ + q0) * NHEAD + h) * HDIM;
    const float* kbase = kp + (size_t)b * SEQ * HDIM;
    const float* vbase = vp + (size_t)b * SEQ * HDIM;

    // load Q tile [64][128] (row stride in gmem = MODEL)
#pragma unroll
    for (int it = 0; it < 8; it++) {
        int f = tid + 256 * it;
        int r = f >> 5;
        int c = (f & 31) << 2;
        *(float4*)&Qs[r * QS_STRIDE + c] =
            *(const float4*)(qbase + (size_t)r * MODEL + c);
    }

    float mrow[4], lrow[4];
    unsigned long long O2[4][4];  // rows {ty+16i}, col pairs {tx*2+32u, +1}
#pragma unroll
    for (int i = 0; i < 4; i++) {
        mrow[i] = __int_as_float(0xff800000);  // -inf
        lrow[i] = 0.f;
#pragma unroll
        for (int u = 0; u < 4; u++) O2[i][u] = 0ull;
    }
    const float rscale = 0.088388347648318447f;  // 1/sqrt(128)

    for (int kv0 = 0; kv0 < SEQ; kv0 += 64) {
        // ---- load K tile ----
#pragma unroll
        for (int it = 0; it < 8; it++) {
            int f = tid + 256 * it;
            int r = f >> 5;
            int c = (f & 31) << 2;
            *(float4*)&KVs[r * QS_STRIDE + c] =
                *(const float4*)(kbase + (size_t)(kv0 + r) * HDIM + c);
        }
        __syncthreads();

        // ---- S = Q @ K^T (k-pair-packed f32x2 accumulation) ----
        unsigned long long s2[4][4];
#pragma unroll
        for (int i = 0; i < 4; i++)
#pragma unroll
            for (int j = 0; j < 4; j++) s2[i][j] = 0ull;

#pragma unroll
        for (int k0 = 0; k0 < HDIM; k0 += 4) {
            ulonglong2 qv[4], kv[4];
#pragma unroll
            for (int i = 0; i < 4; i++)
                qv[i] = *(const ulonglong2*)&Qs[(ty + 16 * i) * QS_STRIDE + k0];
#pragma unroll
            for (int j = 0; j < 4; j++)
                kv[j] = *(const ulonglong2*)&KVs[(tx + 16 * j) * QS_STRIDE + k0];
#pragma unroll
            for (int i = 0; i < 4; i++)
#pragma unroll
                for (int j = 0; j < 4; j++) {
                    ffma2(s2[i][j], qv[i].x, kv[j].x);
                    ffma2(s2[i][j], qv[i].y, kv[j].y);
                }
        }

        // ---- online softmax (row groups = 16 lanes sharing ty) ----
        float p[4][4];
#pragma unroll
        for (int i = 0; i < 4; i++) {
            float s[4];
#pragma unroll
            for (int j = 0; j < 4; j++) {
                float2 f2 = unpack2(s2[i][j]);
                s[j] = (f2.x + f2.y) * rscale;
            }
            float mx = fmaxf(fmaxf(s[0], s[1]), fmaxf(s[2], s[3]));
#pragma unroll
            for (int d = 8; d >= 1; d >>= 1)
                mx = fmaxf(mx, __shfl_xor_sync(0xffffffffu, mx, d));
            float mnew = fmaxf(mrow[i], mx);
            float fac = __expf(mrow[i] - mnew);
            float rsum = 0.f;
#pragma unroll
            for (int j = 0; j < 4; j++) {
                p[i][j] = __expf(s[j] - mnew);
                rsum += p[i][j];
            }
#pragma unroll
            for (int d = 8; d >= 1; d >>= 1)
                rsum += __shfl_xor_sync(0xffffffffu, rsum, d);
            lrow[i] = lrow[i] * fac + rsum;
            mrow[i] = mnew;
            unsigned long long fac2 = pack2(fac, fac);
#pragma unroll
            for (int u = 0; u < 4; u++) O2[i][u] = fmul2(O2[i][u], fac2);
        }

        // ---- stage P to smem ----
#pragma unroll
        for (int i = 0; i < 4; i++)
#pragma unroll
            for (int j = 0; j < 4; j++)
                Ps[(ty + 16 * i) * PS_STRIDE + tx + 16 * j] = p[i][j];
        __syncthreads();  // K reads done + P visible

        // ---- load V tile into the same buffer ----
#pragma unroll
        for (int it = 0; it < 8; it++) {
            int f = tid + 256 * it;
            int r = f >> 5;
            int c = (f & 31) << 2;
            *(float4*)&KVs[r * QS_STRIDE + c] =
                *(const float4*)(vbase + (size_t)(kv0 + r) * HDIM + c);
        }
        __syncthreads();

        // ---- O += P @ V (output cols packed in f32x2 pairs) ----
#pragma unroll 4
        for (int j = 0; j < 64; j++) {
            unsigned long long vv[4];
#pragma unroll
            for (int u = 0; u < 4; u++)
                vv[u] = *(const unsigned long long*)
                        &KVs[j * QS_STRIDE + tx * 2 + 32 * u];
#pragma unroll
            for (int i = 0; i < 4; i++) {
                float pj = Ps[(ty + 16 * i) * PS_STRIDE + j];
                unsigned long long p2 = pack2(pj, pj);
#pragma unroll
                for (int u = 0; u < 4; u++) ffma2(O2[i][u], p2, vv[u]);
            }
        }
        __syncthreads();  // V/P reads done before next tile overwrites
    }

    // ---- normalize + write attn [b,t,h,d] ----
#pragma unroll
    for (int i = 0; i < 4; i++) {
        float rl = 1.0f / lrow[i];
        int r = q0 + ty + 16 * i;
        float* ob = op + (((size_t)b * SEQ + r) * NHEAD + h) * HDIM;
#pragma unroll
        for (int u = 0; u < 4; u++) {
            float2 o = unpack2(O2[i][u]);
            o.x *= rl;
            o.y *= rl;
            *(float2*)&ob[tx * 2 + 32 * u] = o;
        }
    }
}

// ---------------------------------------------------------------------------
extern "C" void kernel_launch(void* const* d_in, const int* in_sizes, int n_in,
                              void* d_out, int out_size) {
    const float* query = (const float*)d_in[0];
    const float* key   = (const float*)d_in[1];
    const float* value = (const float*)d_in[2];
    const float* Wq    = (const float*)d_in[3];
    const float* bq    = (const float*)d_in[4];
    const float* Wo    = (const float*)d_in[5];
    const float* bo    = (const float*)d_in[6];
    float* out = (float*)d_out;

    float *qproj, *attn;
    cudaGetSymbolAddress((void**)&qproj, g_q);
    cudaGetSymbolAddress((void**)&attn, g_attn);

    const int M = BATCH * SEQ;  // 8192
    dim3 gemm_grid(MODEL / 128, M / 128);

    // Stage 1: Q projection
    sgemm_bias_kernel<<<gemm_grid, 256>>>(query, Wq, bq, qproj, M, MODEL, MODEL);

    // Stage 2: flash attention
    cudaFuncSetAttribute(mqa_attn_kernel,
                         cudaFuncAttributeMaxDynamicSharedMemorySize, ATTN_SMEM);
    dim3 attn_grid(SEQ / 64, NHEAD, BATCH);
    mqa_attn_kernel<<<attn_grid, 256, ATTN_SMEM>>>(qproj, key, value, attn);

    // Stage 3: output projection
    sgemm_bias_kernel<<<gemm_grid, 256>>>(attn, Wo, bo, out, M, MODEL, MODEL);
}

// round 6
// speedup vs baseline: 1.3677x; 1.3677x over previous
#include <cuda_runtime.h>
#include <cuda_bf16.h>
#include <cstdint>

// ---------------------------------------------------------------------------
// MultiQueryAttention: out = (softmax((x@Wq) Kᵀ / sqrt(d)) V) @ Wo + bo
// B=4, T=2048, H=16, d=128, model=2048.
// Target is plain sm_100 (no 'a'): tcgen05/TMA unavailable. Tensor cores via
// baseline mma.sync.aligned.m16n8k16 bf16 + ldmatrix.
// Stage 1: Q = query@Wq + bq   (HMMA bf16x3-split GEMM 8192x2048x2048)
// Stage 2: flash attention     (SIMT f32x2, verified R2 kernel, unchanged)
// Stage 3: out = attn@Wo + bo  (HMMA bf16x3-split GEMM)
// ---------------------------------------------------------------------------

#define BATCH 4
#define SEQ   2048
#define NHEAD 16
#define HDIM  128
#define MODEL 2048
#define GK    2048

// ---------------- scratch (__device__ globals: allocation-free rule) -------
__device__ float g_q[(size_t)BATCH * SEQ * MODEL];
__device__ float g_attn[(size_t)BATCH * SEQ * MODEL];
__device__ __nv_bfloat16 g_Ah[(size_t)BATCH * SEQ * MODEL];  // act hi [M,K]
__device__ __nv_bfloat16 g_Al[(size_t)BATCH * SEQ * MODEL];  // act lo [M,K]
__device__ __nv_bfloat16 g_Bh[(size_t)MODEL * MODEL];        // Wt hi  [N,K]
__device__ __nv_bfloat16 g_Bl[(size_t)MODEL * MODEL];        // Wt lo  [N,K]

// ======================= helpers ===========================================
__device__ __forceinline__ uint32_t smem_u32(const void* p) {
    uint32_t a;
    asm("{ .reg .u64 t; cvta.to.shared.u64 t, %1; cvt.u32.u64 %0, t; }"
        : "=r"(a) : "l"(p));
    return a;
}

#define LDSM4(r, addr) \
    asm volatile("ldmatrix.sync.aligned.m8n8.x4.shared.b16 {%0,%1,%2,%3}, [%4];" \
        : "=r"((r)[0]), "=r"((r)[1]), "=r"((r)[2]), "=r"((r)[3]) : "r"(addr))

#define MMA_BF16(d, a, b) \
    asm volatile("mma.sync.aligned.m16n8k16.row.col.f32.bf16.bf16.f32 " \
        "{%0,%1,%2,%3}, {%4,%5,%6,%7}, {%8,%9}, {%0,%1,%2,%3};" \
        : "+f"((d)[0]), "+f"((d)[1]), "+f"((d)[2]), "+f"((d)[3]) \
        : "r"((a)[0]), "r"((a)[1]), "r"((a)[2]), "r"((a)[3]), \
          "r"((b)[0]), "r"((b)[1]))

// ---------------- packed f32x2 helpers (attention kernel) ------------------
__device__ __forceinline__ unsigned long long pack2(float lo, float hi) {
    unsigned long long r;
    asm("mov.b64 %0, {%1, %2};" : "=l"(r) : "f"(lo), "f"(hi));
    return r;
}
__device__ __forceinline__ float2 unpack2(unsigned long long v) {
    float2 r;
    asm("mov.b64 {%0, %1}, %2;" : "=f"(r.x), "=f"(r.y) : "l"(v));
    return r;
}
__device__ __forceinline__ void ffma2(unsigned long long& d, unsigned long long a,
                                      unsigned long long b) {
    asm("fma.rn.f32x2 %0, %1, %2, %0;" : "+l"(d) : "l"(a), "l"(b));
}
__device__ __forceinline__ unsigned long long fmul2(unsigned long long a,
                                                    unsigned long long b) {
    unsigned long long r;
    asm("mul.rn.f32x2 %0, %1, %2;" : "=l"(r) : "l"(a), "l"(b));
    return r;
}

// ===========================================================================
// Split fp32 -> bf16 hi/lo (elementwise, float4-vectorized)
// ===========================================================================
__global__ __launch_bounds__(256) void split_bf16_kernel(
    const float* __restrict__ x, __nv_bfloat16* __restrict__ hi,
    __nv_bfloat16* __restrict__ lo, int n4)
{
    int i = blockIdx.x * 256 + threadIdx.x;
    if (i >= n4) return;
    float4 v = ((const float4*)x)[i];
    __nv_bfloat162 h0 = __floats2bfloat162_rn(v.x, v.y);
    __nv_bfloat162 h1 = __floats2bfloat162_rn(v.z, v.w);
    float2 f0 = __bfloat1622float2(h0);
    float2 f1 = __bfloat1622float2(h1);
    __nv_bfloat162 l0 = __floats2bfloat162_rn(v.x - f0.x, v.y - f0.y);
    __nv_bfloat162 l1 = __floats2bfloat162_rn(v.z - f1.x, v.w - f1.y);
    uint2 ho, loo;
    ho.x = *(uint32_t*)&h0;  ho.y = *(uint32_t*)&h1;
    loo.x = *(uint32_t*)&l0; loo.y = *(uint32_t*)&l1;
    ((uint2*)hi)[i] = ho;
    ((uint2*)lo)[i] = loo;
}

// ===========================================================================
// Transpose + split: W[K,N] fp32 -> Th/Tl[N,K] bf16
// ===========================================================================
__global__ __launch_bounds__(256) void transpose_split_kernel(
    const float* __restrict__ W, __nv_bfloat16* __restrict__ Th,
    __nv_bfloat16* __restrict__ Tl)
{
    __shared__ float tile[32][33];
    const int n0 = blockIdx.x * 32, k0 = blockIdx.y * 32;
    const int tx = threadIdx.x & 31, tyb = threadIdx.x >> 5;
#pragma unroll
    for (int r = tyb; r < 32; r += 8)
        tile[r][tx] = W[(size_t)(k0 + r) * MODEL + n0 + tx];
    __syncthreads();
#pragma unroll
    for (int r = tyb; r < 32; r += 8) {
        float v = tile[tx][r];  // = W[k0+tx][n0+r]
        __nv_bfloat16 h = __float2bfloat16(v);
        size_t o = (size_t)(n0 + r) * GK + k0 + tx;
        Th[o] = h;
        Tl[o] = __float2bfloat16(v - __bfloat162float(h));
    }
}

// ===========================================================================
// HMMA bf16x3 GEMM: C[M,N] = Ah/Al[M,K] x (Bh/Bl[N,K])^T + bias[N]
// CTA 128x128, BK=32, 8 warps (warp tile 64x32), m16n8k16 mma.
// smem tile: 128 rows x 64B, 16B-chunk XOR swizzle q^=(row>>1)&3
//   -> conflict-free for STS (uint4) and all ldmatrix phases.
// 3 products: Ah*Bh + Ah*Bl + Al*Bh (fp32 accum; Al*Bl ~2^-18, dropped).
// ===========================================================================
#define TILE_B 8192             // 128 * 64B
#define STAGE_B (4 * TILE_B)    // Ah, Al, Bh, Bl
#define GEMM_SMEM (2 * STAGE_B) // double buffer = 64KB
#define NKB (GK / 32)           // 64

__device__ __forceinline__ void ldg_tile(uint4 v[2], const __nv_bfloat16* src,
                                         int k0, int tid)
{
#pragma unroll
    for (int i = 0; i < 2; i++) {
        int c = tid + 256 * i;
        int row = c >> 2, q = c & 3;
        v[i] = *(const uint4*)(src + (size_t)row * GK + k0 + q * 8);
    }
}
__device__ __forceinline__ void sts_tile(char* dst, const uint4 v[2], int tid)
{
#pragma unroll
    for (int i = 0; i < 2; i++) {
        int c = tid + 256 * i;
        int row = c >> 2, q = c & 3;
        int qs = q ^ ((row >> 1) & 3);
        *(uint4*)(dst + row * 64 + qs * 16) = v[i];
    }
}
// swizzled smem offset of 16B chunk (row, q)
__device__ __forceinline__ uint32_t sw_off(int row, int q) {
    return (uint32_t)(row * 64 + (q ^ ((row >> 1) & 3)) * 16);
}

__global__ __launch_bounds__(256, 1) void gemm_mma_bf16x3_kernel(
    const __nv_bfloat16* __restrict__ Ah, const __nv_bfloat16* __restrict__ Al,
    const __nv_bfloat16* __restrict__ Bh, const __nv_bfloat16* __restrict__ Bl,
    const float* __restrict__ bias, float* __restrict__ C)
{
    extern __shared__ char sm[];
    const uint32_t smb = smem_u32(sm);
    const int tid = threadIdx.x, lane = tid & 31, wid = tid >> 5;
    const int wm = wid & 1, wn = wid >> 1;       // warp tile: 64x32
    const int row0 = blockIdx.y * 128, col0 = blockIdx.x * 128;

    const __nv_bfloat16* srcs[4] = {
        Ah + (size_t)row0 * GK, Al + (size_t)row0 * GK,
        Bh + (size_t)col0 * GK, Bl + (size_t)col0 * GK };

    float acc[4][4][4];
#pragma unroll
    for (int mt = 0; mt < 4; mt++)
#pragma unroll
        for (int nt = 0; nt < 4; nt++)
#pragma unroll
            for (int e = 0; e < 4; e++) acc[mt][nt][e] = 0.f;

    uint4 v[4][2];
#pragma unroll
    for (int t = 0; t < 4; t++) ldg_tile(v[t], srcs[t], 0, tid);
#pragma unroll
    for (int t = 0; t < 4; t++) sts_tile(sm + t * TILE_B, v[t], tid);

    // lane-dependent fragment rows (within warp tile)
    const int ar = lane & 15;                    // A: row within 16-tile
    const int ac = lane >> 4;                    // A: k-half (0/1)
    const int br = (lane & 7) + ((lane >> 4) << 3);  // B: n row within 16
    const int bc = (lane >> 3) & 1;              // B: k-half (0/1)

    int stage = 0;
    for (int kb = 0; kb < NKB; kb++) {
        __syncthreads();
        if (kb + 1 < NKB) {
#pragma unroll
            for (int t = 0; t < 4; t++)
                ldg_tile(v[t], srcs[t], (kb + 1) * 32, tid);
        }
        const uint32_t sb = smb + stage * STAGE_B;
#pragma unroll
        for (int ks = 0; ks < 2; ks++) {
            uint32_t a_h[4][4], a_l[4][4];
#pragma unroll
            for (int mt = 0; mt < 4; mt++) {
                int rowA = wm * 64 + mt * 16 + ar;
                uint32_t ad = sb + sw_off(rowA, ks * 2 + ac);
                LDSM4(a_h[mt], ad);
                LDSM4(a_l[mt], ad + TILE_B);
            }
            uint32_t b_h[4][2], b_l[4][2];
#pragma unroll
            for (int nb = 0; nb < 2; nb++) {
                int rowB = wn * 32 + nb * 16 + br;
                uint32_t bd = sb + 2 * TILE_B + sw_off(rowB, ks * 2 + bc);
                uint32_t r4[4];
                LDSM4(r4, bd);
                b_h[nb * 2 + 0][0] = r4[0]; b_h[nb * 2 + 0][1] = r4[1];
                b_h[nb * 2 + 1][0] = r4[2]; b_h[nb * 2 + 1][1] = r4[3];
                LDSM4(r4, bd + TILE_B);
                b_l[nb * 2 + 0][0] = r4[0]; b_l[nb * 2 + 0][1] = r4[1];
                b_l[nb * 2 + 1][0] = r4[2]; b_l[nb * 2 + 1][1] = r4[3];
            }
            // product 1: Ah*Bh
#pragma unroll
            for (int mt = 0; mt < 4; mt++)
#pragma unroll
                for (int nt = 0; nt < 4; nt++)
                    MMA_BF16(acc[mt][nt], a_h[mt], b_h[nt]);
            // product 2: Ah*Bl
#pragma unroll
            for (int mt = 0; mt < 4; mt++)
#pragma unroll
                for (int nt = 0; nt < 4; nt++)
                    MMA_BF16(acc[mt][nt], a_h[mt], b_l[nt]);
            // product 3: Al*Bh
#pragma unroll
            for (int mt = 0; mt < 4; mt++)
#pragma unroll
                for (int nt = 0; nt < 4; nt++)
                    MMA_BF16(acc[mt][nt], a_l[mt], b_h[nt]);
        }
        if (kb + 1 < NKB) {
            stage ^= 1;
            char* ds = sm + stage * STAGE_B;
#pragma unroll
            for (int t = 0; t < 4; t++) sts_tile(ds + t * TILE_B, v[t], tid);
        }
    }

    // epilogue: c0,c1 -> (r, c..c+1); c2,c3 -> (r+8, c..c+1)
#pragma unroll
    for (int mt = 0; mt < 4; mt++) {
        int r = row0 + wm * 64 + mt * 16 + (lane >> 2);
#pragma unroll
        for (int nt = 0; nt < 4; nt++) {
            int c = col0 + wn * 32 + nt * 8 + (lane & 3) * 2;
            float2 b2 = *(const float2*)&bias[c];
            float2 o0, o1;
            o0.x = acc[mt][nt][0] + b2.x;
            o0.y = acc[mt][nt][1] + b2.y;
            o1.x = acc[mt][nt][2] + b2.x;
            o1.y = acc[mt][nt][3] + b2.y;
            *(float2*)&C[(size_t)r * MODEL + c] = o0;
            *(float2*)&C[(size_t)(r + 8) * MODEL + c] = o1;
        }
    }
}

// ===========================================================================
// Flash attention (unchanged verified SIMT f32x2 kernel from R2)
// ===========================================================================
#define QS_STRIDE 132
#define PS_STRIDE 80
#define ATTN_SMEM ((2 * 64 * QS_STRIDE + 64 * PS_STRIDE) * (int)sizeof(float))

__global__ __launch_bounds__(256) void mqa_attn_kernel(
    const float* __restrict__ qp, const float* __restrict__ kp,
    const float* __restrict__ vp, float* __restrict__ op)
{
    extern __shared__ float smf[];
    float* Qs  = smf;
    float* KVs = smf + 64 * QS_STRIDE;
    float* Ps  = smf + 2 * 64 * QS_STRIDE;

    const int tid = threadIdx.x;
    const int tx = tid & 15;
    const int ty = tid >> 4;
    const int q0 = blockIdx.x * 64;
    const int h  = blockIdx.y;
    const int b  = blockIdx.z;

    const float* qbase = qp + (((size_t)b * SEQ + q0) * NHEAD + h) * HDIM;
    const float* kbase = kp + (size_t)b * SEQ * HDIM;
    const float* vbase = vp + (size_t)b * SEQ * HDIM;

#pragma unroll
    for (int it = 0; it < 8; it++) {
        int f = tid + 256 * it;
        int r = f >> 5;
        int c = (f & 31) << 2;
        *(float4*)&Qs[r * QS_STRIDE + c] =
            *(const float4*)(qbase + (size_t)r * MODEL + c);
    }

    float mrow[4], lrow[4];
    unsigned long long O2[4][4];
#pragma unroll
    for (int i = 0; i < 4; i++) {
        mrow[i] = __int_as_float(0xff800000);
        lrow[i] = 0.f;
#pragma unroll
        for (int u = 0; u < 4; u++) O2[i][u] = 0ull;
    }
    const float rscale = 0.088388347648318447f;

    for (int kv0 = 0; kv0 < SEQ; kv0 += 64) {
#pragma unroll
        for (int it = 0; it < 8; it++) {
            int f = tid + 256 * it;
            int r = f >> 5;
            int c = (f & 31) << 2;
            *(float4*)&KVs[r * QS_STRIDE + c] =
                *(const float4*)(kbase + (size_t)(kv0 + r) * HDIM + c);
        }
        __syncthreads();

        unsigned long long s2[4][4];
#pragma unroll
        for (int i = 0; i < 4; i++)
#pragma unroll
            for (int j = 0; j < 4; j++) s2[i][j] = 0ull;

#pragma unroll
        for (int k0 = 0; k0 < HDIM; k0 += 4) {
            ulonglong2 qv[4], kv[4];
#pragma unroll
            for (int i = 0; i < 4; i++)
                qv[i] = *(const ulonglong2*)&Qs[(ty + 16 * i) * QS_STRIDE + k0];
#pragma unroll
            for (int j = 0; j < 4; j++)
                kv[j] = *(const ulonglong2*)&KVs[(tx + 16 * j) * QS_STRIDE + k0];
#pragma unroll
            for (int i = 0; i < 4; i++)
#pragma unroll
                for (int j = 0; j < 4; j++) {
                    ffma2(s2[i][j], qv[i].x, kv[j].x);
                    ffma2(s2[i][j], qv[i].y, kv[j].y);
                }
        }

        float p[4][4];
#pragma unroll
        for (int i = 0; i < 4; i++) {
            float s[4];
#pragma unroll
            for (int j = 0; j < 4; j++) {
                float2 f2 = unpack2(s2[i][j]);
                s[j] = (f2.x + f2.y) * rscale;
            }
            float mx = fmaxf(fmaxf(s[0], s[1]), fmaxf(s[2], s[3]));
#pragma unroll
            for (int d = 8; d >= 1; d >>= 1)
                mx = fmaxf(mx, __shfl_xor_sync(0xffffffffu, mx, d));
            float mnew = fmaxf(mrow[i], mx);
            float fac = __expf(mrow[i] - mnew);
            float rsum = 0.f;
#pragma unroll
            for (int j = 0; j < 4; j++) {
                p[i][j] = __expf(s[j] - mnew);
                rsum += p[i][j];
            }
#pragma unroll
            for (int d = 8; d >= 1; d >>= 1)
                rsum += __shfl_xor_sync(0xffffffffu, rsum, d);
            lrow[i] = lrow[i] * fac + rsum;
            mrow[i] = mnew;
            unsigned long long fac2 = pack2(fac, fac);
#pragma unroll
            for (int u = 0; u < 4; u++) O2[i][u] = fmul2(O2[i][u], fac2);
        }

#pragma unroll
        for (int i = 0; i < 4; i++)
#pragma unroll
            for (int j = 0; j < 4; j++)
                Ps[(ty + 16 * i) * PS_STRIDE + tx + 16 * j] = p[i][j];
        __syncthreads();

#pragma unroll
        for (int it = 0; it < 8; it++) {
            int f = tid + 256 * it;
            int r = f >> 5;
            int c = (f & 31) << 2;
            *(float4*)&KVs[r * QS_STRIDE + c] =
                *(const float4*)(vbase + (size_t)(kv0 + r) * HDIM + c);
        }
        __syncthreads();

#pragma unroll 4
        for (int j = 0; j < 64; j++) {
            unsigned long long vv[4];
#pragma unroll
            for (int u = 0; u < 4; u++)
                vv[u] = *(const unsigned long long*)
                        &KVs[j * QS_STRIDE + tx * 2 + 32 * u];
#pragma unroll
            for (int i = 0; i < 4; i++) {
                float pj = Ps[(ty + 16 * i) * PS_STRIDE + j];
                unsigned long long p2 = pack2(pj, pj);
#pragma unroll
                for (int u = 0; u < 4; u++) ffma2(O2[i][u], p2, vv[u]);
            }
        }
        __syncthreads();
    }

#pragma unroll
    for (int i = 0; i < 4; i++) {
        float rl = 1.0f / lrow[i];
        int r = q0 + ty + 16 * i;
        float* ob = op + (((size_t)b * SEQ + r) * NHEAD + h) * HDIM;
#pragma unroll
        for (int u = 0; u < 4; u++) {
            float2 o = unpack2(O2[i][u]);
            o.x *= rl;
            o.y *= rl;
            *(float2*)&ob[tx * 2 + 32 * u] = o;
        }
    }
}

// ===========================================================================
extern "C" void kernel_launch(void* const* d_in, const int* in_sizes, int n_in,
                              void* d_out, int out_size) {
    const float* query = (const float*)d_in[0];
    const float* key   = (const float*)d_in[1];
    const float* value = (const float*)d_in[2];
    const float* Wq    = (const float*)d_in[3];
    const float* bq    = (const float*)d_in[4];
    const float* Wo    = (const float*)d_in[5];
    const float* bo    = (const float*)d_in[6];
    float* out = (float*)d_out;

    float *qproj, *attn;
    __nv_bfloat16 *Ah, *Al, *Bh, *Bl;
    cudaGetSymbolAddress((void**)&qproj, g_q);
    cudaGetSymbolAddress((void**)&attn, g_attn);
    cudaGetSymbolAddress((void**)&Ah, g_Ah);
    cudaGetSymbolAddress((void**)&Al, g_Al);
    cudaGetSymbolAddress((void**)&Bh, g_Bh);
    cudaGetSymbolAddress((void**)&Bl, g_Bl);

    const int M = BATCH * SEQ;             // 8192
    const int n4_act = M * MODEL / 4;
    dim3 tgrid(MODEL / 32, MODEL / 32);
    dim3 ggrid(MODEL / 128, M / 128);      // (16, 64)

    cudaFuncSetAttribute(gemm_mma_bf16x3_kernel,
                         cudaFuncAttributeMaxDynamicSharedMemorySize, GEMM_SMEM);
    cudaFuncSetAttribute(mqa_attn_kernel,
                         cudaFuncAttributeMaxDynamicSharedMemorySize, ATTN_SMEM);

    // Stage 1: Q projection
    split_bf16_kernel<<<(n4_act + 255) / 256, 256>>>(query, Ah, Al, n4_act);
    transpose_split_kernel<<<tgrid, 256>>>(Wq, Bh, Bl);
    gemm_mma_bf16x3_kernel<<<ggrid, 256, GEMM_SMEM>>>(Ah, Al, Bh, Bl, bq, qproj);

    // Stage 2: flash attention
    dim3 attn_grid(SEQ / 64, NHEAD, BATCH);
    mqa_attn_kernel<<<attn_grid, 256, ATTN_SMEM>>>(qproj, key, value, attn);

    // Stage 3: output projection
    split_bf16_kernel<<<(n4_act + 255) / 256, 256>>>(attn, Ah, Al, n4_act);
    transpose_split_kernel<<<tgrid, 256>>>(Wo, Bh, Bl);
    gemm_mma_bf16x3_kernel<<<ggrid, 256, GEMM_SMEM>>>(Ah, Al, Bh, Bl, bo, out);
}